// round 3
// baseline (speedup 1.0000x reference)
#include <cuda_runtime.h>
#include <math.h>

// Fused single-kernel version.
//   yout = tanh(yin @ (w + alpha*hebb) + input)   [1, N]
//   hebb' = (1-eta)*hebb + eta*outer(yin, yout)   [N, N]
//
// Each CTA owns 8 contiguous columns (one 32B DRAM sector per row):
//   Phase A: full column reduction over all 4096 rows (w/alpha streamed
//            evict-first; hebb cached normally -> stays in L2).
//   Phase B: CTA-local tree reduction + tanh -> yout (write to d_out).
//   Phase C: re-walk the same hebb stripe (L2-resident) for the update.
// Single wave: 512 CTAs x 512 threads, no inter-CTA dependencies.

#define N 4096
#define COLS 8                       // columns per CTA (8 x 4B = 32B sector)
#define THREADS 512
#define CPAIRS (COLS / 2)            // 4 float2 column-pairs
#define RGROUPS (THREADS / CPAIRS)   // 128 row groups
#define ITERS (N / RGROUPS)          // 32 rows per thread

__global__ void __launch_bounds__(THREADS) k_fused(
    const float* __restrict__ input,
    const float* __restrict__ yin,
    const float* __restrict__ hebb,
    const float* __restrict__ w,
    const float* __restrict__ alpha,
    const float* __restrict__ eta,
    float* __restrict__ out)          // [yout | hebb_new]
{
    __shared__ float2 red[RGROUPS][CPAIRS];
    __shared__ float2 s_yout[CPAIRS];

    const int t  = threadIdx.x;
    const int cp = t & (CPAIRS - 1);       // column pair 0..3
    const int r  = t >> 2;                 // row group 0..127
    const int j0 = blockIdx.x * COLS;      // CTA's first column
    const int j  = j0 + cp * 2;            // this thread's column pair

    // ---------------- Phase A: column partial sums ----------------
    float2 acc = make_float2(0.f, 0.f);
    {
        const float2* __restrict__ wp = reinterpret_cast<const float2*>(w     + (size_t)r * N + j);
        const float2* __restrict__ ap = reinterpret_cast<const float2*>(alpha + (size_t)r * N + j);
        const float2* __restrict__ hp = reinterpret_cast<const float2*>(hebb  + (size_t)r * N + j);
        const size_t stride2 = (size_t)RGROUPS * (N / 2);   // 128 rows in float2 units

        #pragma unroll 8
        for (int k = 0; k < ITERS; ++k) {
            const float  y  = __ldg(&yin[r + k * RGROUPS]);
            const float2 w2 = __ldcs(wp);   // evict-first: keep L2 for hebb
            const float2 a2 = __ldcs(ap);   // evict-first
            const float2 h2 = __ldg(hp);    // default: hebb stays in L2
            acc.x = fmaf(y, fmaf(a2.x, h2.x, w2.x), acc.x);
            acc.y = fmaf(y, fmaf(a2.y, h2.y, w2.y), acc.y);
            wp += stride2; ap += stride2; hp += stride2;
        }
    }

    // ---------------- Phase B: CTA reduction + tanh ----------------
    red[r][cp] = acc;
    __syncthreads();

    #pragma unroll
    for (int s = RGROUPS / 2; s >= 1; s >>= 1) {
        if (r < s) {
            float2 o = red[r + s][cp];
            float2 m = red[r][cp];
            m.x += o.x; m.y += o.y;
            red[r][cp] = m;
        }
        __syncthreads();
    }

    if (r == 0) {
        const float2 sum = red[0][cp];
        float2 yo;
        yo.x = tanhf(sum.x + __ldg(&input[j]));
        yo.y = tanhf(sum.y + __ldg(&input[j + 1]));
        s_yout[cp] = yo;
        *reinterpret_cast<float2*>(out + j) = yo;   // yout section of d_out
    }
    __syncthreads();

    // ---------------- Phase C: hebb update (hebb from L2) ----------------
    const float  e   = __ldg(eta);
    const float  ome = 1.f - e;
    const float2 yo  = s_yout[cp];

    const float2* __restrict__ hp = reinterpret_cast<const float2*>(hebb + (size_t)r * N + j);
    float2* __restrict__ op = reinterpret_cast<float2*>(out + N + (size_t)r * N + j);
    const size_t stride2 = (size_t)RGROUPS * (N / 2);

    #pragma unroll 8
    for (int k = 0; k < ITERS; ++k) {
        const float  yie = __ldg(&yin[r + k * RGROUPS]) * e;
        const float2 h2  = __ldg(hp);        // should hit L2 (read in phase A)
        float2 r2;
        r2.x = fmaf(ome, h2.x, yie * yo.x);
        r2.y = fmaf(ome, h2.y, yie * yo.y);
        __stcs(op, r2);                      // evict-first write
        hp += stride2; op += stride2;
    }
}

extern "C" void kernel_launch(void* const* d_in, const int* in_sizes, int n_in,
                              void* d_out, int out_size)
{
    const float* input = (const float*)d_in[0];
    const float* yin   = (const float*)d_in[1];
    const float* hebb  = (const float*)d_in[2];
    const float* w     = (const float*)d_in[3];
    const float* alpha = (const float*)d_in[4];
    const float* eta   = (const float*)d_in[5];

    k_fused<<<N / COLS, THREADS>>>(input, yin, hebb, w, alpha, eta, (float*)d_out);
}